// round 4
// baseline (speedup 1.0000x reference)
#include <cuda_runtime.h>
#include <cuda_bf16.h>
#include <math.h>

#define B_   256
#define A_   64
#define G_   978
#define DDRUG 128
#define DCELL 50
#define CELLIN 978
#define DOSEIN 12
#define GLOBAL_ 306   // 128+50+128
#define EXPIN 434
#define E_   4
#define H_   128

#define NCHUNK 8      // k-split for cell L1

// -------- device scratch --------
__device__ float d_gfeat[B_ * GLOBAL_];     // drug [0:128), dose [178:306); cell recomputed locally
__device__ float d_c1p[NCHUNK * B_ * 200];  // cell L1 partials [chunk][row][200]
__device__ float d_U[B_ * E_ * H_];         // [b][e*128+h]
__device__ float d_V[G_ * E_ * H_];         // [g][e*128+h]
__device__ int   d_eidx[B_ * 2];
__device__ float d_gw[B_ * 2];
__device__ float d_biasc[B_];

// =========================================================
// K1 (inputs only), 256 threads:
//   [0,128)    drug atom-sum, 2 rows/block
//   [128,384)  cell L1 partials: 8 k-chunks x 32 row-tiles (RB=8)
//   [384,448)  dose L1+L2 fused: 4 rows/block
//   [448,694)  V = gene_emb @ eW1[:,306:,:]: 123 row-tiles x 2 expert-pairs
// =========================================================
__global__ void __launch_bounds__(256) kernel1(
    const float* __restrict__ drug,
    const float* __restrict__ gex,
    const float* __restrict__ cW1,
    const float* __restrict__ idose,
    const float* __restrict__ dW1, const float* __restrict__ db1,
    const float* __restrict__ dW2, const float* __restrict__ db2,
    const float* __restrict__ gene_emb,
    const float* __restrict__ eW1)
{
    __shared__ __align__(16) float sA[8 * 128];
    const int blk = blockIdx.x;
    const int t = threadIdx.x;

    if (blk < 128) {
        // ---- drug sum ----
        int b = blk * 2 + (t >> 7);
        int d = t & 127;
        const float* p = drug + (size_t)b * A_ * DDRUG + d;
        float s = 0.f;
#pragma unroll
        for (int a = 0; a < A_; a++) s += p[a * DDRUG];
        d_gfeat[b * GLOBAL_ + d] = s;

    } else if (blk < 384) {
        // ---- cell L1 partial ----
        int idx = blk - 128;
        int c = idx >> 5, rt = idx & 31;
        int r0 = rt * 8;
        int k0 = (CELLIN * c) / NCHUNK;
        int k1 = (CELLIN * (c + 1)) / NCHUNK;
        int kc = k1 - k0;                 // 122 or 123
        const int Kp = 124;
        for (int i = t; i < 8 * Kp; i += 256) {
            int r = i / Kp, k = i - r * Kp;
            sA[i] = (k < kc) ? gex[(r0 + r) * CELLIN + k0 + k] : 0.f;
        }
        __syncthreads();
        if (t < 200) {
            float acc[8];
#pragma unroll
            for (int r = 0; r < 8; r++) acc[r] = 0.f;
            int kc4 = kc & ~3;
            for (int k = 0; k < kc4; k += 4) {
                float w0 = cW1[(k0 + k + 0) * 200 + t];
                float w1 = cW1[(k0 + k + 1) * 200 + t];
                float w2 = cW1[(k0 + k + 2) * 200 + t];
                float w3 = cW1[(k0 + k + 3) * 200 + t];
#pragma unroll
                for (int r = 0; r < 8; r++) {
                    float4 x = *reinterpret_cast<const float4*>(sA + r * Kp + k);
                    acc[r] = fmaf(x.x, w0, acc[r]);
                    acc[r] = fmaf(x.y, w1, acc[r]);
                    acc[r] = fmaf(x.z, w2, acc[r]);
                    acc[r] = fmaf(x.w, w3, acc[r]);
                }
            }
            for (int k = kc4; k < kc; k++) {
                float w = cW1[(k0 + k) * 200 + t];
#pragma unroll
                for (int r = 0; r < 8; r++)
                    acc[r] = fmaf(sA[r * Kp + k], w, acc[r]);
            }
#pragma unroll
            for (int r = 0; r < 8; r++)
                d_c1p[(c * B_ + r0 + r) * 200 + t] = acc[r];
        }

    } else if (blk < 448) {
        // ---- dose L1+L2 fused, 4 rows ----
        int r0 = (blk - 384) * 4;
        {
            int row = t >> 6, col = t & 63;
            float a = db1[col];
            const float* x = idose + (r0 + row) * DOSEIN;
#pragma unroll
            for (int k = 0; k < DOSEIN; k++)
                a = fmaf(x[k], dW1[k * 64 + col], a);
            sA[row * 64 + col] = fmaxf(a, 0.f);
        }
        __syncthreads();
#pragma unroll
        for (int rr = 0; rr < 2; rr++) {
            int row = rr * 2 + (t >> 7);
            int col = t & 127;
            float a = db2[col];
#pragma unroll 4
            for (int k = 0; k < 64; k += 4) {
                float w0 = dW2[(k + 0) * 128 + col];
                float w1 = dW2[(k + 1) * 128 + col];
                float w2 = dW2[(k + 2) * 128 + col];
                float w3 = dW2[(k + 3) * 128 + col];
                float4 x = *reinterpret_cast<const float4*>(sA + row * 64 + k);
                a = fmaf(x.x, w0, a);
                a = fmaf(x.y, w1, a);
                a = fmaf(x.z, w2, a);
                a = fmaf(x.w, w3, a);
            }
            d_gfeat[(r0 + row) * GLOBAL_ + 178 + col] = fmaxf(a, 0.f);
        }

    } else {
        // ---- V: 8 genes x 2 experts ----
        int idx = blk - 448;
        int rt = idx >> 1, ep = idx & 1;
        int r0 = rt * 8;
        int e = ep * 2 + (t >> 7), h = t & 127;
        for (int i = t; i < 8 * 128; i += 256) {
            int r = i >> 7, k = i & 127;
            sA[i] = (r0 + r < G_) ? gene_emb[(r0 + r) * 128 + k] : 0.f;
        }
        __syncthreads();
        float acc[8];
#pragma unroll
        for (int r = 0; r < 8; r++) acc[r] = 0.f;
        const float* Wv = eW1 + (size_t)e * EXPIN * H_ + (size_t)GLOBAL_ * H_ + h;
#pragma unroll 1
        for (int k = 0; k < 128; k += 4) {
            float w0 = Wv[(k + 0) * H_];
            float w1 = Wv[(k + 1) * H_];
            float w2 = Wv[(k + 2) * H_];
            float w3 = Wv[(k + 3) * H_];
#pragma unroll
            for (int r = 0; r < 8; r++) {
                float4 x = *reinterpret_cast<const float4*>(sA + r * 128 + k);
                acc[r] = fmaf(x.x, w0, acc[r]);
                acc[r] = fmaf(x.y, w1, acc[r]);
                acc[r] = fmaf(x.z, w2, acc[r]);
                acc[r] = fmaf(x.w, w3, acc[r]);
            }
        }
#pragma unroll
        for (int r = 0; r < 8; r++)
            if (r0 + r < G_) d_V[(r0 + r) * (E_ * H_) + e * H_ + h] = acc[r];
    }
}

// =========================================================
// K2, 256 threads, 4 rows/block. Every block locally rebuilds its rows'
// gfeat (drug+dose from global, cell L2/L3 recomputed from L1 partials).
//   [0,128)   U blocks: tile = blk>>1, expert pair = blk&1
//   [128,192) gate blocks (also write cellOut)
// =========================================================
__global__ void __launch_bounds__(256) kernel2(
    const float* __restrict__ cb1,
    const float* __restrict__ cW2, const float* __restrict__ cb2,
    const float* __restrict__ cW3, const float* __restrict__ cb3,
    const float* __restrict__ gW1, const float* __restrict__ gb1,
    const float* __restrict__ gW2, const float* __restrict__ gb2,
    const float* __restrict__ eW1, const float* __restrict__ eb1,
    const float* __restrict__ eb2,
    float* __restrict__ cellOut)
{
    __shared__ __align__(16) float sC1[4 * 200];
    __shared__ __align__(16) float sH[4 * 100];
    __shared__ __align__(16) float sG[4 * 308];
    const int blk = blockIdx.x;
    const int t = threadIdx.x;
    const bool isGate = (blk >= 128);
    const int r0 = isGate ? (blk - 128) * 4 : (blk >> 1) * 4;

    // gfeat drug+dose parts -> sG; zero cell region + pads
    for (int i = t; i < 4 * 308; i += 256) {
        int r = i / 308, k = i - r * 308;
        float v = 0.f;
        if (k < 128 || (k >= 178 && k < GLOBAL_))
            v = d_gfeat[(r0 + r) * GLOBAL_ + k];
        sG[i] = v;
    }
    // cell L1 reduce + bias + relu
    for (int i = t; i < 4 * 200; i += 256) {
        int r = i / 200, k = i - r * 200;
        float s = cb1[k];
#pragma unroll
        for (int c = 0; c < NCHUNK; c++)
            s += d_c1p[(c * B_ + r0 + r) * 200 + k];
        sC1[i] = fmaxf(s, 0.f);
    }
    __syncthreads();
    // cell L2: 200 -> 100
    if (t < 100) {
        float acc[4];
#pragma unroll
        for (int r = 0; r < 4; r++) acc[r] = cb2[t];
        for (int k = 0; k < 200; k += 4) {
            float w0 = cW2[(k + 0) * 100 + t];
            float w1 = cW2[(k + 1) * 100 + t];
            float w2 = cW2[(k + 2) * 100 + t];
            float w3 = cW2[(k + 3) * 100 + t];
#pragma unroll
            for (int r = 0; r < 4; r++) {
                float4 x = *reinterpret_cast<const float4*>(sC1 + r * 200 + k);
                acc[r] = fmaf(x.x, w0, acc[r]);
                acc[r] = fmaf(x.y, w1, acc[r]);
                acc[r] = fmaf(x.z, w2, acc[r]);
                acc[r] = fmaf(x.w, w3, acc[r]);
            }
        }
#pragma unroll
        for (int r = 0; r < 4; r++)
            sH[r * 100 + t] = fmaxf(acc[r], 0.f);
    }
    __syncthreads();
    // cell L3: 100 -> 50, into sG[:,128:178]
    if (t < 50) {
        float acc[4];
#pragma unroll
        for (int r = 0; r < 4; r++) acc[r] = cb3[t];
        for (int k = 0; k < 100; k += 4) {
            float w0 = cW3[(k + 0) * 50 + t];
            float w1 = cW3[(k + 1) * 50 + t];
            float w2 = cW3[(k + 2) * 50 + t];
            float w3 = cW3[(k + 3) * 50 + t];
#pragma unroll
            for (int r = 0; r < 4; r++) {
                float4 x = *reinterpret_cast<const float4*>(sH + r * 100 + k);
                acc[r] = fmaf(x.x, w0, acc[r]);
                acc[r] = fmaf(x.y, w1, acc[r]);
                acc[r] = fmaf(x.z, w2, acc[r]);
                acc[r] = fmaf(x.w, w3, acc[r]);
            }
        }
#pragma unroll
        for (int r = 0; r < 4; r++) {
            float v = fmaxf(acc[r], 0.f);
            sG[r * 308 + 128 + t] = v;
            if (isGate && cellOut) cellOut[(r0 + r) * DCELL + t] = v;
        }
    }
    __syncthreads();

    if (!isGate) {
        // ---- U: 4 rows x 2 experts ----
        int ep = blk & 1;
        int e = ep * 2 + (t >> 7), h = t & 127;
        float acc[4];
        float bb = eb1[e * H_ + h];
#pragma unroll
        for (int r = 0; r < 4; r++) acc[r] = bb;
        const float* Wp = eW1 + (size_t)e * EXPIN * H_ + h;
#pragma unroll 1
        for (int k = 0; k < 308; k += 4) {
            float w0 = (k + 0 < GLOBAL_) ? Wp[(k + 0) * H_] : 0.f;
            float w1 = (k + 1 < GLOBAL_) ? Wp[(k + 1) * H_] : 0.f;
            float w2 = (k + 2 < GLOBAL_) ? Wp[(k + 2) * H_] : 0.f;
            float w3 = (k + 3 < GLOBAL_) ? Wp[(k + 3) * H_] : 0.f;
#pragma unroll
            for (int r = 0; r < 4; r++) {
                float4 x = *reinterpret_cast<const float4*>(sG + r * 308 + k);
                acc[r] = fmaf(x.x, w0, acc[r]);
                acc[r] = fmaf(x.y, w1, acc[r]);
                acc[r] = fmaf(x.z, w2, acc[r]);
                acc[r] = fmaf(x.w, w3, acc[r]);
            }
        }
#pragma unroll
        for (int r = 0; r < 4; r++)
            d_U[(r0 + r) * (E_ * H_) + e * H_ + h] = acc[r];
    } else {
        // ---- gating ----
        __shared__ float sHp[2][4][128];
        __shared__ float sL[16];
        {   // hidden: k halves [0,152) / [152,308)
            int half = t >> 7, h = t & 127;
            int kA = half * 152, kB = half ? 308 : 152;
            float acc[4] = {0.f, 0.f, 0.f, 0.f};
            for (int k = kA; k < kB; k += 4) {
                float w0 = (k + 0 < GLOBAL_) ? gW1[(k + 0) * 128 + h] : 0.f;
                float w1 = (k + 1 < GLOBAL_) ? gW1[(k + 1) * 128 + h] : 0.f;
                float w2 = (k + 2 < GLOBAL_) ? gW1[(k + 2) * 128 + h] : 0.f;
                float w3 = (k + 3 < GLOBAL_) ? gW1[(k + 3) * 128 + h] : 0.f;
#pragma unroll
                for (int r = 0; r < 4; r++) {
                    float4 x = *reinterpret_cast<const float4*>(sG + r * 308 + k);
                    acc[r] = fmaf(x.x, w0, acc[r]);
                    acc[r] = fmaf(x.y, w1, acc[r]);
                    acc[r] = fmaf(x.z, w2, acc[r]);
                    acc[r] = fmaf(x.w, w3, acc[r]);
                }
            }
#pragma unroll
            for (int r = 0; r < 4; r++) sHp[half][r][h] = acc[r];
        }
        __syncthreads();
        if (t < 128) {
            float bb = gb1[t];
#pragma unroll
            for (int r = 0; r < 4; r++)
                sH[r * 128 + t] = fmaxf(sHp[0][r][t] + sHp[1][r][t] + bb, 0.f);
        }
        __syncthreads();
        if (t < 16) {
            int r = t >> 2, e = t & 3;
            float a = gb2[e];
            for (int k = 0; k < 128; k++)
                a = fmaf(sH[r * 128 + k], gW2[k * 4 + e], a);
            sL[t] = a;
        }
        __syncthreads();
        if (t < 4) {
            int b = r0 + t;
            float v[4];
#pragma unroll
            for (int j = 0; j < 4; j++) v[j] = sL[t * 4 + j];
            int i0 = 0;
#pragma unroll
            for (int j = 1; j < 4; j++) if (v[j] > v[i0]) i0 = j;
            int i1 = (i0 == 0) ? 1 : 0;
#pragma unroll
            for (int j = 0; j < 4; j++) if (j != i0 && v[j] > v[i1]) i1 = j;
            float m  = fmaxf(v[i0], v[i1]);
            float e0 = __expf(v[i0] - m), e1 = __expf(v[i1] - m);
            float inv = 1.f / (e0 + e1);
            float w0 = e0 * inv, w1 = e1 * inv;
            d_eidx[2 * b]     = i0;
            d_eidx[2 * b + 1] = i1;
            d_gw[2 * b]       = w0;
            d_gw[2 * b + 1]   = w1;
            d_biasc[b]        = w0 * eb2[i0] + w1 * eb2[i1];
        }
    }
    // NOTE: sH reuse in gate path happens after __syncthreads(), safe.
}

// =========================================================
// Combine v2: warp = one b; lanes = (gene-quad, h-octet): 8 lanes/gene,
// 4 genes per pass, 3-level reduce. Gate weights folded into W2 regs.
// =========================================================
__global__ void __launch_bounds__(512) combine_kernel(
    const float* __restrict__ expW2, float* __restrict__ pred)
{
    __shared__ __align__(16) float4 sV[16 * 128];
    const int g0   = blockIdx.x * 16;
    const int warp = threadIdx.x >> 5;
    const int lane = threadIdx.x & 31;
    const int b    = blockIdx.y * 16 + warp;
    const int oct  = lane & 7;       // h-octet: h in [oct*16, oct*16+16)
    const int quad = lane >> 3;      // gene sub-index within group of 4
    const int nG   = (G_ - g0) < 16 ? (G_ - g0) : 16;

    const float4* V4 = reinterpret_cast<const float4*>(d_V);
    for (int i = threadIdx.x; i < nG * 128; i += blockDim.x)
        sV[i] = V4[g0 * 128 + i];
    __syncthreads();

    const int   e0  = d_eidx[2 * b], e1 = d_eidx[2 * b + 1];
    const float gw0 = d_gw[2 * b],   gw1 = d_gw[2 * b + 1];
    const float bc  = d_biasc[b];

    const float4* U4 = reinterpret_cast<const float4*>(d_U) + b * 128;
    const float4* W4 = reinterpret_cast<const float4*>(expW2);
    float4 u0[4], u1[4], w0[4], w1[4];
#pragma unroll
    for (int j = 0; j < 4; j++) {
        u0[j] = U4[e0 * 32 + oct * 4 + j];
        u1[j] = U4[e1 * 32 + oct * 4 + j];
        float4 a = W4[e0 * 32 + oct * 4 + j];
        a.x *= gw0; a.y *= gw0; a.z *= gw0; a.w *= gw0;
        w0[j] = a;
        float4 c = W4[e1 * 32 + oct * 4 + j];
        c.x *= gw1; c.y *= gw1; c.z *= gw1; c.w *= gw1;
        w1[j] = c;
    }

#pragma unroll 2
    for (int gt = 0; gt < 4; gt++) {
        int gene = gt * 4 + quad;
        const float4* vp = sV + gene * 128;
        float acc = 0.f;
#pragma unroll
        for (int j = 0; j < 4; j++) {
            float4 v = vp[e0 * 32 + oct * 4 + j];
            acc = fmaf(fmaxf(u0[j].x + v.x, 0.f), w0[j].x, acc);
            acc = fmaf(fmaxf(u0[j].y + v.y, 0.f), w0[j].y, acc);
            acc = fmaf(fmaxf(u0[j].z + v.z, 0.f), w0[j].z, acc);
            acc = fmaf(fmaxf(u0[j].w + v.w, 0.f), w0[j].w, acc);
        }
#pragma unroll
        for (int j = 0; j < 4; j++) {
            float4 v = vp[e1 * 32 + oct * 4 + j];
            acc = fmaf(fmaxf(u1[j].x + v.x, 0.f), w1[j].x, acc);
            acc = fmaf(fmaxf(u1[j].y + v.y, 0.f), w1[j].y, acc);
            acc = fmaf(fmaxf(u1[j].z + v.z, 0.f), w1[j].z, acc);
            acc = fmaf(fmaxf(u1[j].w + v.w, 0.f), w1[j].w, acc);
        }
        // reduce across 8 h-octets (lanes differing in bits 0..2)
        acc += __shfl_xor_sync(0xffffffffu, acc, 1);
        acc += __shfl_xor_sync(0xffffffffu, acc, 2);
        acc += __shfl_xor_sync(0xffffffffu, acc, 4);
        if (oct == 0 && gene < nG)
            pred[b * G_ + g0 + gene] = acc + bc;
    }
}

// =========================================================
extern "C" void kernel_launch(void* const* d_in, const int* in_sizes, int n_in,
                              void* d_out, int out_size)
{
    const float* drug_atom = (const float*)d_in[0];
    const float* gex       = (const float*)d_in[1];
    const float* idose     = (const float*)d_in[2];
    const float* cW1 = (const float*)d_in[3];  const float* cb1 = (const float*)d_in[4];
    const float* cW2 = (const float*)d_in[5];  const float* cb2 = (const float*)d_in[6];
    const float* cW3 = (const float*)d_in[7];  const float* cb3 = (const float*)d_in[8];
    const float* dW1 = (const float*)d_in[9];  const float* db1 = (const float*)d_in[10];
    const float* dW2 = (const float*)d_in[11]; const float* db2 = (const float*)d_in[12];
    const float* gene_emb = (const float*)d_in[13];
    const float* gW1 = (const float*)d_in[14]; const float* gb1 = (const float*)d_in[15];
    const float* gW2 = (const float*)d_in[16]; const float* gb2 = (const float*)d_in[17];
    const float* eW1 = (const float*)d_in[18]; const float* eb1 = (const float*)d_in[19];
    const float* eW2 = (const float*)d_in[20]; const float* eb2 = (const float*)d_in[21];

    float* pred = (float*)d_out;
    float* cellOut = (out_size >= B_ * G_ + B_ * DCELL) ? pred + B_ * G_ : nullptr;

    kernel1<<<694, 256>>>(drug_atom, gex, cW1, idose, dW1, db1, dW2, db2,
                          gene_emb, eW1);
    kernel2<<<192, 256>>>(cb1, cW2, cb2, cW3, cb3, gW1, gb1, gW2, gb2,
                          eW1, eb1, eb2, cellOut);
    dim3 cg((G_ + 15) / 16, B_ / 16);
    combine_kernel<<<cg, 512>>>(eW2, pred);
}

// round 5
// speedup vs baseline: 1.4652x; 1.4652x over previous
#include <cuda_runtime.h>
#include <cuda_bf16.h>
#include <math.h>

#define B_   256
#define A_   64
#define G_   978
#define DDRUG 128
#define DCELL 50
#define CELLIN 978
#define DOSEIN 12
#define GLOBAL_ 306   // 128+50+128
#define EXPIN 434
#define E_   4
#define H_   128

#define NCHUNK 8      // k-split for cell L1

// -------- device scratch --------
__device__ float d_gfeat[B_ * GLOBAL_];
__device__ float d_c1p[NCHUNK * B_ * 200];  // cell L1 partials [chunk][row][200]
__device__ float d_d1[B_ * 64];
__device__ float d_U[B_ * E_ * H_];         // [b][e*128+h]
__device__ float d_V[G_ * E_ * H_];         // [g][e*128+h]
__device__ int   d_eidx[B_ * 2];
__device__ float d_gw[B_ * 2];
__device__ float d_biasc[B_];

// =========================================================
// Stage A (inputs only), 256 threads:
//   [0,128)    drug atom-sum, 2 rows/block
//   [128,384)  cell L1 partials: 8 k-chunks x 32 row-tiles (RB=8)
//   [384,448)  dose L1: 4 rows/block
//   [448,694)  V = gene_emb @ eW1[:,306:,:]: 123 row-tiles x 2 expert-pairs
// =========================================================
__global__ void __launch_bounds__(256) stageA(
    const float* __restrict__ drug,
    const float* __restrict__ gex,
    const float* __restrict__ cW1,
    const float* __restrict__ idose,
    const float* __restrict__ dW1, const float* __restrict__ db1,
    const float* __restrict__ gene_emb,
    const float* __restrict__ eW1)
{
    __shared__ __align__(16) float sA[8 * 128];
    const int blk = blockIdx.x;
    const int t = threadIdx.x;

    if (blk < 128) {
        // ---- drug sum ----
        int b = blk * 2 + (t >> 7);
        int d = t & 127;
        const float* p = drug + (size_t)b * A_ * DDRUG + d;
        float s = 0.f;
#pragma unroll
        for (int a = 0; a < A_; a++) s += p[a * DDRUG];
        d_gfeat[b * GLOBAL_ + d] = s;

    } else if (blk < 384) {
        // ---- cell L1 partial: chunk c, rows r0..r0+7 ----
        int idx = blk - 128;
        int c = idx >> 5, rt = idx & 31;
        int r0 = rt * 8;
        int k0 = (CELLIN * c) / NCHUNK;
        int k1 = (CELLIN * (c + 1)) / NCHUNK;
        int kc = k1 - k0;                 // 122 or 123
        const int Kp = 124;
        for (int i = t; i < 8 * Kp; i += 256) {
            int r = i / Kp, k = i - r * Kp;
            sA[i] = (k < kc) ? gex[(r0 + r) * CELLIN + k0 + k] : 0.f;
        }
        __syncthreads();
        if (t < 200) {
            float acc[8];
#pragma unroll
            for (int r = 0; r < 8; r++) acc[r] = 0.f;
            int k = 0;
            for (; k + 8 <= kc; k += 8) {
                float w[8];
#pragma unroll
                for (int j = 0; j < 8; j++)
                    w[j] = cW1[(k0 + k + j) * 200 + t];
#pragma unroll
                for (int r = 0; r < 8; r++) {
                    float4 xa = *reinterpret_cast<const float4*>(sA + r * Kp + k);
                    float4 xb = *reinterpret_cast<const float4*>(sA + r * Kp + k + 4);
                    acc[r] = fmaf(xa.x, w[0], acc[r]);
                    acc[r] = fmaf(xa.y, w[1], acc[r]);
                    acc[r] = fmaf(xa.z, w[2], acc[r]);
                    acc[r] = fmaf(xa.w, w[3], acc[r]);
                    acc[r] = fmaf(xb.x, w[4], acc[r]);
                    acc[r] = fmaf(xb.y, w[5], acc[r]);
                    acc[r] = fmaf(xb.z, w[6], acc[r]);
                    acc[r] = fmaf(xb.w, w[7], acc[r]);
                }
            }
            for (; k < kc; k++) {
                float w = cW1[(k0 + k) * 200 + t];
#pragma unroll
                for (int r = 0; r < 8; r++)
                    acc[r] = fmaf(sA[r * Kp + k], w, acc[r]);
            }
#pragma unroll
            for (int r = 0; r < 8; r++)
                d_c1p[(c * B_ + r0 + r) * 200 + t] = acc[r];
        }

    } else if (blk < 448) {
        // ---- dose L1 ----
        int row = (blk - 384) * 4 + (t >> 6);
        int col = t & 63;
        float a = db1[col];
        const float* x = idose + row * DOSEIN;
#pragma unroll
        for (int k = 0; k < DOSEIN; k++)
            a = fmaf(x[k], dW1[k * 64 + col], a);
        d_d1[row * 64 + col] = fmaxf(a, 0.f);

    } else {
        // ---- V: 8 genes x 2 experts ----
        int idx = blk - 448;
        int rt = idx >> 1, ep = idx & 1;
        int r0 = rt * 8;
        int e = ep * 2 + (t >> 7), h = t & 127;
        for (int i = t; i < 8 * 128; i += 256) {
            int r = i >> 7, k = i & 127;
            sA[i] = (r0 + r < G_) ? gene_emb[(r0 + r) * 128 + k] : 0.f;
        }
        __syncthreads();
        float acc[8];
#pragma unroll
        for (int r = 0; r < 8; r++) acc[r] = 0.f;
        const float* Wv = eW1 + (size_t)e * EXPIN * H_ + (size_t)GLOBAL_ * H_ + h;
#pragma unroll 1
        for (int k = 0; k < 128; k += 8) {
            float w[8];
#pragma unroll
            for (int j = 0; j < 8; j++)
                w[j] = Wv[(k + j) * H_];
#pragma unroll
            for (int r = 0; r < 8; r++) {
                float4 xa = *reinterpret_cast<const float4*>(sA + r * 128 + k);
                float4 xb = *reinterpret_cast<const float4*>(sA + r * 128 + k + 4);
                acc[r] = fmaf(xa.x, w[0], acc[r]);
                acc[r] = fmaf(xa.y, w[1], acc[r]);
                acc[r] = fmaf(xa.z, w[2], acc[r]);
                acc[r] = fmaf(xa.w, w[3], acc[r]);
                acc[r] = fmaf(xb.x, w[4], acc[r]);
                acc[r] = fmaf(xb.y, w[5], acc[r]);
                acc[r] = fmaf(xb.z, w[6], acc[r]);
                acc[r] = fmaf(xb.w, w[7], acc[r]);
            }
        }
#pragma unroll
        for (int r = 0; r < 8; r++)
            if (r0 + r < G_) d_V[(r0 + r) * (E_ * H_) + e * H_ + h] = acc[r];
    }
}

// =========================================================
// Stage BC, 256 threads:
//   [0,64)   cell L2+L3 fused, 4 rows/block (reduce L1 partials in smem)
//   [64,128) dose L2, 4 rows/block
// =========================================================
__global__ void __launch_bounds__(256) stageBC(
    const float* __restrict__ cb1,
    const float* __restrict__ cW2, const float* __restrict__ cb2,
    const float* __restrict__ cW3, const float* __restrict__ cb3,
    const float* __restrict__ dW2, const float* __restrict__ db2,
    float* __restrict__ cellOut)
{
    __shared__ __align__(16) float sA[4 * 200];
    __shared__ __align__(16) float sH[4 * 100];
    const int blk = blockIdx.x;
    const int t = threadIdx.x;

    if (blk < 64) {
        int r0 = blk * 4;
        for (int i = t; i < 4 * 200; i += 256) {
            int r = i / 200, k = i - r * 200;
            float s = cb1[k];
#pragma unroll
            for (int c = 0; c < NCHUNK; c++)
                s += d_c1p[(c * B_ + r0 + r) * 200 + k];
            sA[i] = fmaxf(s, 0.f);
        }
        __syncthreads();
        // L2: 200 -> 100 (unroll 8, 25 iters)
        if (t < 100) {
            float acc[4];
#pragma unroll
            for (int r = 0; r < 4; r++) acc[r] = cb2[t];
            for (int k = 0; k < 200; k += 8) {
                float w[8];
#pragma unroll
                for (int j = 0; j < 8; j++)
                    w[j] = cW2[(k + j) * 100 + t];
#pragma unroll
                for (int r = 0; r < 4; r++) {
                    float4 xa = *reinterpret_cast<const float4*>(sA + r * 200 + k);
                    float4 xb = *reinterpret_cast<const float4*>(sA + r * 200 + k + 4);
                    acc[r] = fmaf(xa.x, w[0], acc[r]);
                    acc[r] = fmaf(xa.y, w[1], acc[r]);
                    acc[r] = fmaf(xa.z, w[2], acc[r]);
                    acc[r] = fmaf(xa.w, w[3], acc[r]);
                    acc[r] = fmaf(xb.x, w[4], acc[r]);
                    acc[r] = fmaf(xb.y, w[5], acc[r]);
                    acc[r] = fmaf(xb.z, w[6], acc[r]);
                    acc[r] = fmaf(xb.w, w[7], acc[r]);
                }
            }
#pragma unroll
            for (int r = 0; r < 4; r++)
                sH[r * 100 + t] = fmaxf(acc[r], 0.f);
        }
        __syncthreads();
        // L3: 100 -> 50
        if (t < 50) {
            float acc[4];
#pragma unroll
            for (int r = 0; r < 4; r++) acc[r] = cb3[t];
            for (int k = 0; k < 100; k += 4) {
                float w0 = cW3[(k + 0) * 50 + t];
                float w1 = cW3[(k + 1) * 50 + t];
                float w2 = cW3[(k + 2) * 50 + t];
                float w3 = cW3[(k + 3) * 50 + t];
#pragma unroll
                for (int r = 0; r < 4; r++) {
                    float4 x = *reinterpret_cast<const float4*>(sH + r * 100 + k);
                    acc[r] = fmaf(x.x, w0, acc[r]);
                    acc[r] = fmaf(x.y, w1, acc[r]);
                    acc[r] = fmaf(x.z, w2, acc[r]);
                    acc[r] = fmaf(x.w, w3, acc[r]);
                }
            }
#pragma unroll
            for (int r = 0; r < 4; r++) {
                float v = fmaxf(acc[r], 0.f);
                d_gfeat[(r0 + r) * GLOBAL_ + 128 + t] = v;
                if (cellOut) cellOut[(r0 + r) * DCELL + t] = v;
            }
        }
    } else {
        // dose L2: 64 -> 128
        int r0 = (blk - 64) * 4;
        for (int i = t; i < 4 * 64; i += 256) {
            int r = i >> 6, k = i & 63;
            sA[i] = d_d1[(r0 + r) * 64 + k];
        }
        __syncthreads();
        if (t < 128) {
            float acc[4];
#pragma unroll
            for (int r = 0; r < 4; r++) acc[r] = db2[t];
            for (int k = 0; k < 64; k += 8) {
                float w[8];
#pragma unroll
                for (int j = 0; j < 8; j++)
                    w[j] = dW2[(k + j) * 128 + t];
#pragma unroll
                for (int r = 0; r < 4; r++) {
                    float4 xa = *reinterpret_cast<const float4*>(sA + r * 64 + k);
                    float4 xb = *reinterpret_cast<const float4*>(sA + r * 64 + k + 4);
                    acc[r] = fmaf(xa.x, w[0], acc[r]);
                    acc[r] = fmaf(xa.y, w[1], acc[r]);
                    acc[r] = fmaf(xa.z, w[2], acc[r]);
                    acc[r] = fmaf(xa.w, w[3], acc[r]);
                    acc[r] = fmaf(xb.x, w[4], acc[r]);
                    acc[r] = fmaf(xb.y, w[5], acc[r]);
                    acc[r] = fmaf(xb.z, w[6], acc[r]);
                    acc[r] = fmaf(xb.w, w[7], acc[r]);
                }
            }
#pragma unroll
            for (int r = 0; r < 4; r++)
                d_gfeat[(r0 + r) * GLOBAL_ + 178 + t] = fmaxf(acc[r], 0.f);
        }
    }
}

// =========================================================
// Stage DE, 256 threads:
//   [0,64)   gating: 4 rows/block, hidden GEMM k-split in half
//   [64,128) U: 8 rows x 2 experts per block
// =========================================================
__global__ void __launch_bounds__(256) stageDE(
    const float* __restrict__ gW1, const float* __restrict__ gb1,
    const float* __restrict__ gW2, const float* __restrict__ gb2,
    const float* __restrict__ eW1, const float* __restrict__ eb1,
    const float* __restrict__ eb2)
{
    __shared__ __align__(16) float sG[8 * 308];
    const int blk = blockIdx.x;
    const int t = threadIdx.x;

    if (blk < 64) {
        __shared__ float sHp[2][4][128];
        __shared__ float sH[4 * 128];
        __shared__ float sL[16];
        int b0 = blk * 4;
        for (int i = t; i < 4 * 308; i += 256) {
            int r = i / 308, k = i - r * 308;
            sG[i] = (k < GLOBAL_) ? d_gfeat[(b0 + r) * GLOBAL_ + k] : 0.f;
        }
        __syncthreads();
        {   // hidden halves: [0,152) and [152,306)
            int half = t >> 7, h = t & 127;
            float acc[4] = {0.f, 0.f, 0.f, 0.f};
            int kA = half ? 152 : 0;
            int kE = half ? 304 : 152;   // 8-aligned span; tail below
            for (int k = kA; k < kE; k += 8) {
                float w[8];
#pragma unroll
                for (int j = 0; j < 8; j++)
                    w[j] = gW1[(k + j) * 128 + h];
#pragma unroll
                for (int r = 0; r < 4; r++) {
                    float4 xa = *reinterpret_cast<const float4*>(sG + r * 308 + k);
                    float4 xb = *reinterpret_cast<const float4*>(sG + r * 308 + k + 4);
                    acc[r] = fmaf(xa.x, w[0], acc[r]);
                    acc[r] = fmaf(xa.y, w[1], acc[r]);
                    acc[r] = fmaf(xa.z, w[2], acc[r]);
                    acc[r] = fmaf(xa.w, w[3], acc[r]);
                    acc[r] = fmaf(xb.x, w[4], acc[r]);
                    acc[r] = fmaf(xb.y, w[5], acc[r]);
                    acc[r] = fmaf(xb.z, w[6], acc[r]);
                    acc[r] = fmaf(xb.w, w[7], acc[r]);
                }
            }
            if (half) {
                for (int k = 304; k < GLOBAL_; k++) {
                    float w = gW1[k * 128 + h];
#pragma unroll
                    for (int r = 0; r < 4; r++)
                        acc[r] = fmaf(sG[r * 308 + k], w, acc[r]);
                }
            }
#pragma unroll
            for (int r = 0; r < 4; r++) sHp[half][r][h] = acc[r];
        }
        __syncthreads();
        if (t < 128) {
            float bb = gb1[t];
#pragma unroll
            for (int r = 0; r < 4; r++)
                sH[r * 128 + t] = fmaxf(sHp[0][r][t] + sHp[1][r][t] + bb, 0.f);
        }
        __syncthreads();
        if (t < 16) {
            int r = t >> 2, e = t & 3;
            float a = gb2[e];
            for (int k = 0; k < 128; k++)
                a = fmaf(sH[r * 128 + k], gW2[k * 4 + e], a);
            sL[t] = a;
        }
        __syncthreads();
        if (t < 4) {
            int b = b0 + t;
            float v[4];
#pragma unroll
            for (int j = 0; j < 4; j++) v[j] = sL[t * 4 + j];
            int i0 = 0;
#pragma unroll
            for (int j = 1; j < 4; j++) if (v[j] > v[i0]) i0 = j;
            int i1 = (i0 == 0) ? 1 : 0;
#pragma unroll
            for (int j = 0; j < 4; j++) if (j != i0 && v[j] > v[i1]) i1 = j;
            float m  = fmaxf(v[i0], v[i1]);
            float e0 = __expf(v[i0] - m), e1 = __expf(v[i1] - m);
            float inv = 1.f / (e0 + e1);
            float w0 = e0 * inv, w1 = e1 * inv;
            d_eidx[2 * b]     = i0;
            d_eidx[2 * b + 1] = i1;
            d_gw[2 * b]       = w0;
            d_gw[2 * b + 1]   = w1;
            d_biasc[b]        = w0 * eb2[i0] + w1 * eb2[i1];
        }
    } else {
        // U: rows r0..r0+7, experts ep*2 + (t>>7)
        int idx = blk - 64;
        int rt = idx >> 1, ep = idx & 1;
        int r0 = rt * 8;
        int e = ep * 2 + (t >> 7), h = t & 127;
        for (int i = t; i < 8 * 308; i += 256) {
            int r = i / 308, k = i - r * 308;
            sG[i] = (k < GLOBAL_) ? d_gfeat[(r0 + r) * GLOBAL_ + k] : 0.f;
        }
        __syncthreads();
        float acc[8];
        float bb = eb1[e * H_ + h];
#pragma unroll
        for (int r = 0; r < 8; r++) acc[r] = bb;
        const float* Wp = eW1 + (size_t)e * EXPIN * H_ + h;
#pragma unroll 1
        for (int k = 0; k < 304; k += 8) {
            float w[8];
#pragma unroll
            for (int j = 0; j < 8; j++)
                w[j] = Wp[(k + j) * H_];
#pragma unroll
            for (int r = 0; r < 8; r++) {
                float4 xa = *reinterpret_cast<const float4*>(sG + r * 308 + k);
                float4 xb = *reinterpret_cast<const float4*>(sG + r * 308 + k + 4);
                acc[r] = fmaf(xa.x, w[0], acc[r]);
                acc[r] = fmaf(xa.y, w[1], acc[r]);
                acc[r] = fmaf(xa.z, w[2], acc[r]);
                acc[r] = fmaf(xa.w, w[3], acc[r]);
                acc[r] = fmaf(xb.x, w[4], acc[r]);
                acc[r] = fmaf(xb.y, w[5], acc[r]);
                acc[r] = fmaf(xb.z, w[6], acc[r]);
                acc[r] = fmaf(xb.w, w[7], acc[r]);
            }
        }
        for (int k = 304; k < GLOBAL_; k++) {
            float w = Wp[k * H_];
#pragma unroll
            for (int r = 0; r < 8; r++)
                acc[r] = fmaf(sG[r * 308 + k], w, acc[r]);
        }
#pragma unroll
        for (int r = 0; r < 8; r++)
            d_U[(r0 + r) * (E_ * H_) + e * H_ + h] = acc[r];
    }
}

// =========================================================
// Combine (v1, proven): pred[b,g] = sum_{e in top2} gw*(sum_h relu(U+V)*W2) + biasc
// 16 warps (one b each), 16-gene V tile in smem, consecutive-float4 reads.
// =========================================================
__global__ void __launch_bounds__(512) combine_kernel(
    const float* __restrict__ expW2, float* __restrict__ pred)
{
    __shared__ float4 sV[16 * 128];
    __shared__ float  sOut[16][17];
    const int g0   = blockIdx.x * 16;
    const int warp = threadIdx.x >> 5;
    const int lane = threadIdx.x & 31;
    const int b    = blockIdx.y * 16 + warp;
    const int nG   = (G_ - g0) < 16 ? (G_ - g0) : 16;

    const float4* V4 = reinterpret_cast<const float4*>(d_V);
    for (int i = threadIdx.x; i < nG * 128; i += blockDim.x)
        sV[i] = V4[g0 * 128 + i];
    __syncthreads();

    const int   e0  = d_eidx[2 * b], e1 = d_eidx[2 * b + 1];
    const float gw0 = d_gw[2 * b],   gw1 = d_gw[2 * b + 1];
    const float bc  = d_biasc[b];

    const float4* U4 = reinterpret_cast<const float4*>(d_U) + b * 128;
    const float4 u0  = U4[e0 * 32 + lane];
    const float4 u1  = U4[e1 * 32 + lane];
    const float4* W4 = reinterpret_cast<const float4*>(expW2);
    const float4 w20 = W4[e0 * 32 + lane];
    const float4 w21 = W4[e1 * 32 + lane];

    for (int gi = 0; gi < nG; gi++) {
        float4 v = sV[gi * 128 + e0 * 32 + lane];
        float t0 =           fmaxf(u0.x + v.x, 0.f) * w20.x;
        t0 = fmaf(fmaxf(u0.y + v.y, 0.f), w20.y, t0);
        t0 = fmaf(fmaxf(u0.z + v.z, 0.f), w20.z, t0);
        t0 = fmaf(fmaxf(u0.w + v.w, 0.f), w20.w, t0);
        v = sV[gi * 128 + e1 * 32 + lane];
        float t1 =           fmaxf(u1.x + v.x, 0.f) * w21.x;
        t1 = fmaf(fmaxf(u1.y + v.y, 0.f), w21.y, t1);
        t1 = fmaf(fmaxf(u1.z + v.z, 0.f), w21.z, t1);
        t1 = fmaf(fmaxf(u1.w + v.w, 0.f), w21.w, t1);
        float p = gw0 * t0 + gw1 * t1;
#pragma unroll
        for (int o = 16; o; o >>= 1)
            p += __shfl_xor_sync(0xffffffffu, p, o);
        if (lane == 0) sOut[warp][gi] = p + bc;
    }
    __syncwarp();
    if (lane < nG)
        pred[b * G_ + g0 + lane] = sOut[warp][lane];
}

// =========================================================
extern "C" void kernel_launch(void* const* d_in, const int* in_sizes, int n_in,
                              void* d_out, int out_size)
{
    const float* drug_atom = (const float*)d_in[0];
    const float* gex       = (const float*)d_in[1];
    const float* idose     = (const float*)d_in[2];
    const float* cW1 = (const float*)d_in[3];  const float* cb1 = (const float*)d_in[4];
    const float* cW2 = (const float*)d_in[5];  const float* cb2 = (const float*)d_in[6];
    const float* cW3 = (const float*)d_in[7];  const float* cb3 = (const float*)d_in[8];
    const float* dW1 = (const float*)d_in[9];  const float* db1 = (const float*)d_in[10];
    const float* dW2 = (const float*)d_in[11]; const float* db2 = (const float*)d_in[12];
    const float* gene_emb = (const float*)d_in[13];
    const float* gW1 = (const float*)d_in[14]; const float* gb1 = (const float*)d_in[15];
    const float* gW2 = (const float*)d_in[16]; const float* gb2 = (const float*)d_in[17];
    const float* eW1 = (const float*)d_in[18]; const float* eb1 = (const float*)d_in[19];
    const float* eW2 = (const float*)d_in[20]; const float* eb2 = (const float*)d_in[21];

    float* pred = (float*)d_out;
    float* cellOut = (out_size >= B_ * G_ + B_ * DCELL) ? pred + B_ * G_ : nullptr;

    stageA<<<694, 256>>>(drug_atom, gex, cW1, idose, dW1, db1, gene_emb, eW1);
    stageBC<<<128, 256>>>(cb1, cW2, cb2, cW3, cb3, dW2, db2, cellOut);
    stageDE<<<128, 256>>>(gW1, gb1, gW2, gb2, eW1, eb1, eb2);
    dim3 cg((G_ + 15) / 16, B_ / 16);
    combine_kernel<<<cg, 512>>>(eW2, pred);
}

// round 6
// speedup vs baseline: 1.5120x; 1.0319x over previous
#include <cuda_runtime.h>
#include <cuda_bf16.h>
#include <math.h>

#define B_   256
#define A_   64
#define G_   978
#define DDRUG 128
#define DCELL 50
#define CELLIN 978
#define DOSEIN 12
#define GLOBAL_ 306   // 128+50+128
#define EXPIN 434
#define E_   4
#define H_   128

#define NCHUNK 8      // k-split for cell L1
#define GT    24      // combine gene tile (24*128*16B = 48KB smem)

// -------- device scratch --------
__device__ float d_gfeat[B_ * GLOBAL_];
__device__ float d_c1p[NCHUNK * B_ * 200];  // cell L1 partials [chunk][row][200]
__device__ float d_d1[B_ * 64];
__device__ float d_U[B_ * E_ * H_];         // [b][e*128+h]
__device__ float d_V[G_ * E_ * H_];         // [g][e*128+h]
__device__ int   d_eidx[B_ * 2];
__device__ float d_gw[B_ * 2];
__device__ float d_biasc[B_];

// =========================================================
// Stage A (inputs only), 256 threads:
//   [0,128)    drug atom-sum, 2 rows/block
//   [128,384)  cell L1 partials: 8 k-chunks x 32 row-tiles (RB=8)
//   [384,448)  dose L1: 4 rows/block
//   [448,694)  V = gene_emb @ eW1[:,306:,:]: 123 row-tiles x 2 expert-pairs
// =========================================================
__global__ void __launch_bounds__(256) stageA(
    const float* __restrict__ drug,
    const float* __restrict__ gex,
    const float* __restrict__ cW1,
    const float* __restrict__ idose,
    const float* __restrict__ dW1, const float* __restrict__ db1,
    const float* __restrict__ gene_emb,
    const float* __restrict__ eW1)
{
    __shared__ __align__(16) float sA[8 * 128];
    const int blk = blockIdx.x;
    const int t = threadIdx.x;

    if (blk < 128) {
        int b = blk * 2 + (t >> 7);
        int d = t & 127;
        const float* p = drug + (size_t)b * A_ * DDRUG + d;
        float s = 0.f;
#pragma unroll
        for (int a = 0; a < A_; a++) s += p[a * DDRUG];
        d_gfeat[b * GLOBAL_ + d] = s;

    } else if (blk < 384) {
        int idx = blk - 128;
        int c = idx >> 5, rt = idx & 31;
        int r0 = rt * 8;
        int k0 = (CELLIN * c) / NCHUNK;
        int k1 = (CELLIN * (c + 1)) / NCHUNK;
        int kc = k1 - k0;                 // 122 or 123
        const int Kp = 124;
        for (int i = t; i < 8 * Kp; i += 256) {
            int r = i / Kp, k = i - r * Kp;
            sA[i] = (k < kc) ? gex[(r0 + r) * CELLIN + k0 + k] : 0.f;
        }
        __syncthreads();
        if (t < 200) {
            float acc[8];
#pragma unroll
            for (int r = 0; r < 8; r++) acc[r] = 0.f;
            int k = 0;
            for (; k + 8 <= kc; k += 8) {
                float w[8];
#pragma unroll
                for (int j = 0; j < 8; j++)
                    w[j] = cW1[(k0 + k + j) * 200 + t];
#pragma unroll
                for (int r = 0; r < 8; r++) {
                    float4 xa = *reinterpret_cast<const float4*>(sA + r * Kp + k);
                    float4 xb = *reinterpret_cast<const float4*>(sA + r * Kp + k + 4);
                    acc[r] = fmaf(xa.x, w[0], acc[r]);
                    acc[r] = fmaf(xa.y, w[1], acc[r]);
                    acc[r] = fmaf(xa.z, w[2], acc[r]);
                    acc[r] = fmaf(xa.w, w[3], acc[r]);
                    acc[r] = fmaf(xb.x, w[4], acc[r]);
                    acc[r] = fmaf(xb.y, w[5], acc[r]);
                    acc[r] = fmaf(xb.z, w[6], acc[r]);
                    acc[r] = fmaf(xb.w, w[7], acc[r]);
                }
            }
            for (; k < kc; k++) {
                float w = cW1[(k0 + k) * 200 + t];
#pragma unroll
                for (int r = 0; r < 8; r++)
                    acc[r] = fmaf(sA[r * Kp + k], w, acc[r]);
            }
#pragma unroll
            for (int r = 0; r < 8; r++)
                d_c1p[(c * B_ + r0 + r) * 200 + t] = acc[r];
        }

    } else if (blk < 448) {
        int row = (blk - 384) * 4 + (t >> 6);
        int col = t & 63;
        float a = db1[col];
        const float* x = idose + row * DOSEIN;
#pragma unroll
        for (int k = 0; k < DOSEIN; k++)
            a = fmaf(x[k], dW1[k * 64 + col], a);
        d_d1[row * 64 + col] = fmaxf(a, 0.f);

    } else {
        int idx = blk - 448;
        int rt = idx >> 1, ep = idx & 1;
        int r0 = rt * 8;
        int e = ep * 2 + (t >> 7), h = t & 127;
        for (int i = t; i < 8 * 128; i += 256) {
            int r = i >> 7, k = i & 127;
            sA[i] = (r0 + r < G_) ? gene_emb[(r0 + r) * 128 + k] : 0.f;
        }
        __syncthreads();
        float acc[8];
#pragma unroll
        for (int r = 0; r < 8; r++) acc[r] = 0.f;
        const float* Wv = eW1 + (size_t)e * EXPIN * H_ + (size_t)GLOBAL_ * H_ + h;
#pragma unroll 1
        for (int k = 0; k < 128; k += 8) {
            float w[8];
#pragma unroll
            for (int j = 0; j < 8; j++)
                w[j] = Wv[(k + j) * H_];
#pragma unroll
            for (int r = 0; r < 8; r++) {
                float4 xa = *reinterpret_cast<const float4*>(sA + r * 128 + k);
                float4 xb = *reinterpret_cast<const float4*>(sA + r * 128 + k + 4);
                acc[r] = fmaf(xa.x, w[0], acc[r]);
                acc[r] = fmaf(xa.y, w[1], acc[r]);
                acc[r] = fmaf(xa.z, w[2], acc[r]);
                acc[r] = fmaf(xa.w, w[3], acc[r]);
                acc[r] = fmaf(xb.x, w[4], acc[r]);
                acc[r] = fmaf(xb.y, w[5], acc[r]);
                acc[r] = fmaf(xb.z, w[6], acc[r]);
                acc[r] = fmaf(xb.w, w[7], acc[r]);
            }
        }
#pragma unroll
        for (int r = 0; r < 8; r++)
            if (r0 + r < G_) d_V[(r0 + r) * (E_ * H_) + e * H_ + h] = acc[r];
    }
}

// =========================================================
// Stage BC, 256 threads:
//   [0,64)   cell L2+L3 fused, 4 rows/block
//   [64,128) dose L2, 4 rows/block
// =========================================================
__global__ void __launch_bounds__(256) stageBC(
    const float* __restrict__ cb1,
    const float* __restrict__ cW2, const float* __restrict__ cb2,
    const float* __restrict__ cW3, const float* __restrict__ cb3,
    const float* __restrict__ dW2, const float* __restrict__ db2,
    float* __restrict__ cellOut)
{
    __shared__ __align__(16) float sA[4 * 200];
    __shared__ __align__(16) float sH[4 * 100];
    const int blk = blockIdx.x;
    const int t = threadIdx.x;

    if (blk < 64) {
        int r0 = blk * 4;
        for (int i = t; i < 4 * 200; i += 256) {
            int r = i / 200, k = i - r * 200;
            float s = cb1[k];
#pragma unroll
            for (int c = 0; c < NCHUNK; c++)
                s += d_c1p[(c * B_ + r0 + r) * 200 + k];
            sA[i] = fmaxf(s, 0.f);
        }
        __syncthreads();
        if (t < 100) {
            float acc[4];
#pragma unroll
            for (int r = 0; r < 4; r++) acc[r] = cb2[t];
            for (int k = 0; k < 200; k += 8) {
                float w[8];
#pragma unroll
                for (int j = 0; j < 8; j++)
                    w[j] = cW2[(k + j) * 100 + t];
#pragma unroll
                for (int r = 0; r < 4; r++) {
                    float4 xa = *reinterpret_cast<const float4*>(sA + r * 200 + k);
                    float4 xb = *reinterpret_cast<const float4*>(sA + r * 200 + k + 4);
                    acc[r] = fmaf(xa.x, w[0], acc[r]);
                    acc[r] = fmaf(xa.y, w[1], acc[r]);
                    acc[r] = fmaf(xa.z, w[2], acc[r]);
                    acc[r] = fmaf(xa.w, w[3], acc[r]);
                    acc[r] = fmaf(xb.x, w[4], acc[r]);
                    acc[r] = fmaf(xb.y, w[5], acc[r]);
                    acc[r] = fmaf(xb.z, w[6], acc[r]);
                    acc[r] = fmaf(xb.w, w[7], acc[r]);
                }
            }
#pragma unroll
            for (int r = 0; r < 4; r++)
                sH[r * 100 + t] = fmaxf(acc[r], 0.f);
        }
        __syncthreads();
        if (t < 50) {
            float acc[4];
#pragma unroll
            for (int r = 0; r < 4; r++) acc[r] = cb3[t];
            for (int k = 0; k < 100; k += 4) {
                float w0 = cW3[(k + 0) * 50 + t];
                float w1 = cW3[(k + 1) * 50 + t];
                float w2 = cW3[(k + 2) * 50 + t];
                float w3 = cW3[(k + 3) * 50 + t];
#pragma unroll
                for (int r = 0; r < 4; r++) {
                    float4 x = *reinterpret_cast<const float4*>(sH + r * 100 + k);
                    acc[r] = fmaf(x.x, w0, acc[r]);
                    acc[r] = fmaf(x.y, w1, acc[r]);
                    acc[r] = fmaf(x.z, w2, acc[r]);
                    acc[r] = fmaf(x.w, w3, acc[r]);
                }
            }
#pragma unroll
            for (int r = 0; r < 4; r++) {
                float v = fmaxf(acc[r], 0.f);
                d_gfeat[(r0 + r) * GLOBAL_ + 128 + t] = v;
                if (cellOut) cellOut[(r0 + r) * DCELL + t] = v;
            }
        }
    } else {
        int r0 = (blk - 64) * 4;
        for (int i = t; i < 4 * 64; i += 256) {
            int r = i >> 6, k = i & 63;
            sA[i] = d_d1[(r0 + r) * 64 + k];
        }
        __syncthreads();
        if (t < 128) {
            float acc[4];
#pragma unroll
            for (int r = 0; r < 4; r++) acc[r] = db2[t];
            for (int k = 0; k < 64; k += 8) {
                float w[8];
#pragma unroll
                for (int j = 0; j < 8; j++)
                    w[j] = dW2[(k + j) * 128 + t];
#pragma unroll
                for (int r = 0; r < 4; r++) {
                    float4 xa = *reinterpret_cast<const float4*>(sA + r * 64 + k);
                    float4 xb = *reinterpret_cast<const float4*>(sA + r * 64 + k + 4);
                    acc[r] = fmaf(xa.x, w[0], acc[r]);
                    acc[r] = fmaf(xa.y, w[1], acc[r]);
                    acc[r] = fmaf(xa.z, w[2], acc[r]);
                    acc[r] = fmaf(xa.w, w[3], acc[r]);
                    acc[r] = fmaf(xb.x, w[4], acc[r]);
                    acc[r] = fmaf(xb.y, w[5], acc[r]);
                    acc[r] = fmaf(xb.z, w[6], acc[r]);
                    acc[r] = fmaf(xb.w, w[7], acc[r]);
                }
            }
#pragma unroll
            for (int r = 0; r < 4; r++)
                d_gfeat[(r0 + r) * GLOBAL_ + 178 + t] = fmaxf(acc[r], 0.f);
        }
    }
}

// =========================================================
// Stage DE, 256 threads:
//   [0,64)   gating: 4 rows/block, hidden GEMM k-split in half
//   [64,128) U: 8 rows x 2 experts per block
// =========================================================
__global__ void __launch_bounds__(256) stageDE(
    const float* __restrict__ gW1, const float* __restrict__ gb1,
    const float* __restrict__ gW2, const float* __restrict__ gb2,
    const float* __restrict__ eW1, const float* __restrict__ eb1,
    const float* __restrict__ eb2)
{
    __shared__ __align__(16) float sG[8 * 308];
    const int blk = blockIdx.x;
    const int t = threadIdx.x;

    if (blk < 64) {
        __shared__ float sHp[2][4][128];
        __shared__ float sH[4 * 128];
        __shared__ float sL[16];
        int b0 = blk * 4;
        for (int i = t; i < 4 * 308; i += 256) {
            int r = i / 308, k = i - r * 308;
            sG[i] = (k < GLOBAL_) ? d_gfeat[(b0 + r) * GLOBAL_ + k] : 0.f;
        }
        __syncthreads();
        {
            int half = t >> 7, h = t & 127;
            float acc[4] = {0.f, 0.f, 0.f, 0.f};
            int kA = half ? 152 : 0;
            int kE = half ? 304 : 152;
            for (int k = kA; k < kE; k += 8) {
                float w[8];
#pragma unroll
                for (int j = 0; j < 8; j++)
                    w[j] = gW1[(k + j) * 128 + h];
#pragma unroll
                for (int r = 0; r < 4; r++) {
                    float4 xa = *reinterpret_cast<const float4*>(sG + r * 308 + k);
                    float4 xb = *reinterpret_cast<const float4*>(sG + r * 308 + k + 4);
                    acc[r] = fmaf(xa.x, w[0], acc[r]);
                    acc[r] = fmaf(xa.y, w[1], acc[r]);
                    acc[r] = fmaf(xa.z, w[2], acc[r]);
                    acc[r] = fmaf(xa.w, w[3], acc[r]);
                    acc[r] = fmaf(xb.x, w[4], acc[r]);
                    acc[r] = fmaf(xb.y, w[5], acc[r]);
                    acc[r] = fmaf(xb.z, w[6], acc[r]);
                    acc[r] = fmaf(xb.w, w[7], acc[r]);
                }
            }
            if (half) {
                for (int k = 304; k < GLOBAL_; k++) {
                    float w = gW1[k * 128 + h];
#pragma unroll
                    for (int r = 0; r < 4; r++)
                        acc[r] = fmaf(sG[r * 308 + k], w, acc[r]);
                }
            }
#pragma unroll
            for (int r = 0; r < 4; r++) sHp[half][r][h] = acc[r];
        }
        __syncthreads();
        if (t < 128) {
            float bb = gb1[t];
#pragma unroll
            for (int r = 0; r < 4; r++)
                sH[r * 128 + t] = fmaxf(sHp[0][r][t] + sHp[1][r][t] + bb, 0.f);
        }
        __syncthreads();
        if (t < 16) {
            int r = t >> 2, e = t & 3;
            float a = gb2[e];
            for (int k = 0; k < 128; k++)
                a = fmaf(sH[r * 128 + k], gW2[k * 4 + e], a);
            sL[t] = a;
        }
        __syncthreads();
        if (t < 4) {
            int b = b0 + t;
            float v[4];
#pragma unroll
            for (int j = 0; j < 4; j++) v[j] = sL[t * 4 + j];
            int i0 = 0;
#pragma unroll
            for (int j = 1; j < 4; j++) if (v[j] > v[i0]) i0 = j;
            int i1 = (i0 == 0) ? 1 : 0;
#pragma unroll
            for (int j = 0; j < 4; j++) if (j != i0 && v[j] > v[i1]) i1 = j;
            float m  = fmaxf(v[i0], v[i1]);
            float e0 = __expf(v[i0] - m), e1 = __expf(v[i1] - m);
            float inv = 1.f / (e0 + e1);
            float w0 = e0 * inv, w1 = e1 * inv;
            d_eidx[2 * b]     = i0;
            d_eidx[2 * b + 1] = i1;
            d_gw[2 * b]       = w0;
            d_gw[2 * b + 1]   = w1;
            d_biasc[b]        = w0 * eb2[i0] + w1 * eb2[i1];
        }
    } else {
        int idx = blk - 64;
        int rt = idx >> 1, ep = idx & 1;
        int r0 = rt * 8;
        int e = ep * 2 + (t >> 7), h = t & 127;
        for (int i = t; i < 8 * 308; i += 256) {
            int r = i / 308, k = i - r * 308;
            sG[i] = (k < GLOBAL_) ? d_gfeat[(r0 + r) * GLOBAL_ + k] : 0.f;
        }
        __syncthreads();
        float acc[8];
        float bb = eb1[e * H_ + h];
#pragma unroll
        for (int r = 0; r < 8; r++) acc[r] = bb;
        const float* Wp = eW1 + (size_t)e * EXPIN * H_ + h;
#pragma unroll 1
        for (int k = 0; k < 304; k += 8) {
            float w[8];
#pragma unroll
            for (int j = 0; j < 8; j++)
                w[j] = Wp[(k + j) * H_];
#pragma unroll
            for (int r = 0; r < 8; r++) {
                float4 xa = *reinterpret_cast<const float4*>(sG + r * 308 + k);
                float4 xb = *reinterpret_cast<const float4*>(sG + r * 308 + k + 4);
                acc[r] = fmaf(xa.x, w[0], acc[r]);
                acc[r] = fmaf(xa.y, w[1], acc[r]);
                acc[r] = fmaf(xa.z, w[2], acc[r]);
                acc[r] = fmaf(xa.w, w[3], acc[r]);
                acc[r] = fmaf(xb.x, w[4], acc[r]);
                acc[r] = fmaf(xb.y, w[5], acc[r]);
                acc[r] = fmaf(xb.z, w[6], acc[r]);
                acc[r] = fmaf(xb.w, w[7], acc[r]);
            }
        }
        for (int k = 304; k < GLOBAL_; k++) {
            float w = Wp[k * H_];
#pragma unroll
            for (int r = 0; r < 8; r++)
                acc[r] = fmaf(sG[r * 308 + k], w, acc[r]);
        }
#pragma unroll
        for (int r = 0; r < 8; r++)
            d_U[(r0 + r) * (E_ * H_) + e * H_ + h] = acc[r];
    }
}

// =========================================================
// Combine v3: warp = one b, 24-gene V tile, paired-gene merged reduce.
// For a gene pair (p0,p1): fold at offset 16 independently, select halves,
// single 4-level butterfly reduces both; lane0/lane16 store directly.
// =========================================================
__global__ void __launch_bounds__(512) combine_kernel(
    const float* __restrict__ expW2, float* __restrict__ pred)
{
    __shared__ float4 sV[GT * 128];      // 24 * 2KB = 48KB
    const int g0   = blockIdx.x * GT;
    const int warp = threadIdx.x >> 5;
    const int lane = threadIdx.x & 31;
    const int b    = blockIdx.y * 16 + warp;
    const int nG   = (G_ - g0) < GT ? (G_ - g0) : GT;   // 24 or 18 (even)

    const float4* V4 = reinterpret_cast<const float4*>(d_V);
    for (int i = threadIdx.x; i < nG * 128; i += blockDim.x)
        sV[i] = V4[g0 * 128 + i];
    __syncthreads();

    const int   e0  = d_eidx[2 * b], e1 = d_eidx[2 * b + 1];
    const float gw0 = d_gw[2 * b],   gw1 = d_gw[2 * b + 1];
    const float bc  = d_biasc[b];

    const float4* U4 = reinterpret_cast<const float4*>(d_U) + b * 128;
    const float4 u0  = U4[e0 * 32 + lane];
    const float4 u1  = U4[e1 * 32 + lane];
    const float4* W4 = reinterpret_cast<const float4*>(expW2);
    float4 w20 = W4[e0 * 32 + lane];
    w20.x *= gw0; w20.y *= gw0; w20.z *= gw0; w20.w *= gw0;
    float4 w21 = W4[e1 * 32 + lane];
    w21.x *= gw1; w21.y *= gw1; w21.z *= gw1; w21.w *= gw1;

#pragma unroll 2
    for (int gi = 0; gi < nG; gi += 2) {
        // load both genes' V up front (independent LDS)
        float4 va0 = sV[(gi + 0) * 128 + e0 * 32 + lane];
        float4 va1 = sV[(gi + 0) * 128 + e1 * 32 + lane];
        float4 vb0 = sV[(gi + 1) * 128 + e0 * 32 + lane];
        float4 vb1 = sV[(gi + 1) * 128 + e1 * 32 + lane];

        float p0 =           fmaxf(u0.x + va0.x, 0.f) * w20.x;
        p0 = fmaf(fmaxf(u0.y + va0.y, 0.f), w20.y, p0);
        p0 = fmaf(fmaxf(u0.z + va0.z, 0.f), w20.z, p0);
        p0 = fmaf(fmaxf(u0.w + va0.w, 0.f), w20.w, p0);
        p0 = fmaf(fmaxf(u1.x + va1.x, 0.f), w21.x, p0);
        p0 = fmaf(fmaxf(u1.y + va1.y, 0.f), w21.y, p0);
        p0 = fmaf(fmaxf(u1.z + va1.z, 0.f), w21.z, p0);
        p0 = fmaf(fmaxf(u1.w + va1.w, 0.f), w21.w, p0);

        float p1 =           fmaxf(u0.x + vb0.x, 0.f) * w20.x;
        p1 = fmaf(fmaxf(u0.y + vb0.y, 0.f), w20.y, p1);
        p1 = fmaf(fmaxf(u0.z + vb0.z, 0.f), w20.z, p1);
        p1 = fmaf(fmaxf(u0.w + vb0.w, 0.f), w20.w, p1);
        p1 = fmaf(fmaxf(u1.x + vb1.x, 0.f), w21.x, p1);
        p1 = fmaf(fmaxf(u1.y + vb1.y, 0.f), w21.y, p1);
        p1 = fmaf(fmaxf(u1.z + vb1.z, 0.f), w21.z, p1);
        p1 = fmaf(fmaxf(u1.w + vb1.w, 0.f), w21.w, p1);

        // merged reduction: fold 16 independently, select, 4-level butterfly
        float z0 = p0 + __shfl_xor_sync(0xffffffffu, p0, 16);
        float z1 = p1 + __shfl_xor_sync(0xffffffffu, p1, 16);
        float s  = (lane & 16) ? z1 : z0;
        s += __shfl_xor_sync(0xffffffffu, s, 8);
        s += __shfl_xor_sync(0xffffffffu, s, 4);
        s += __shfl_xor_sync(0xffffffffu, s, 2);
        s += __shfl_xor_sync(0xffffffffu, s, 1);
        if (lane == 0)
            pred[b * G_ + g0 + gi] = s + bc;
        else if (lane == 16)
            pred[b * G_ + g0 + gi + 1] = s + bc;
    }
}

// =========================================================
extern "C" void kernel_launch(void* const* d_in, const int* in_sizes, int n_in,
                              void* d_out, int out_size)
{
    const float* drug_atom = (const float*)d_in[0];
    const float* gex       = (const float*)d_in[1];
    const float* idose     = (const float*)d_in[2];
    const float* cW1 = (const float*)d_in[3];  const float* cb1 = (const float*)d_in[4];
    const float* cW2 = (const float*)d_in[5];  const float* cb2 = (const float*)d_in[6];
    const float* cW3 = (const float*)d_in[7];  const float* cb3 = (const float*)d_in[8];
    const float* dW1 = (const float*)d_in[9];  const float* db1 = (const float*)d_in[10];
    const float* dW2 = (const float*)d_in[11]; const float* db2 = (const float*)d_in[12];
    const float* gene_emb = (const float*)d_in[13];
    const float* gW1 = (const float*)d_in[14]; const float* gb1 = (const float*)d_in[15];
    const float* gW2 = (const float*)d_in[16]; const float* gb2 = (const float*)d_in[17];
    const float* eW1 = (const float*)d_in[18]; const float* eb1 = (const float*)d_in[19];
    const float* eW2 = (const float*)d_in[20]; const float* eb2 = (const float*)d_in[21];

    float* pred = (float*)d_out;
    float* cellOut = (out_size >= B_ * G_ + B_ * DCELL) ? pred + B_ * G_ : nullptr;

    stageA<<<694, 256>>>(drug_atom, gex, cW1, idose, dW1, db1, gene_emb, eW1);
    stageBC<<<128, 256>>>(cb1, cW2, cb2, cW3, cb3, dW2, db2, cellOut);
    stageDE<<<128, 256>>>(gW1, gb1, gW2, gb2, eW1, eb1, eb2);
    dim3 cg((G_ + GT - 1) / GT, B_ / 16);
    combine_kernel<<<cg, 512>>>(eW2, pred);
}